// round 15
// baseline (speedup 1.0000x reference)
#include <cuda_runtime.h>
#include <cuda_bf16.h>
#include <cstddef>

// Problem constants (from reference)
#define BATCH   8192
#define BOX     10
#define PAIR    90                    // BOX*(BOX-1)
#define NUM_QT  65
#define NUM_OT  151
#define PLANE   (NUM_OT * NUM_OT)     // 22801 floats per (qt,pair) plane
#define NPLANES (NUM_QT * PAIR)       // 5850
#define NTHREADS 512
#define BK_THREADS 1024
#define BK_WARPS   (BK_THREADS / 32)      // 32
#define BK_PER_LANE (BATCH / BK_THREADS)  // 8 values per lane

// Scratch: per-qt compacted batch lists (disjoint segments, no prefix needed)
__device__ int g_list[NUM_QT * BATCH];   // 2 MB
__device__ int g_cnt[NUM_QT];

// ---------------------------------------------------------------------------
// Kernel 1 (PDL primary): per-qt compaction, latency-batched (one memory
// round trip). Fires launch_dependents at entry so kernel 2 overlaps.
// ---------------------------------------------------------------------------
__global__ __launch_bounds__(BK_THREADS) void bucket_kernel(
        const int* __restrict__ qus_type) {
    asm volatile("griddepcontrol.launch_dependents;");

    __shared__ int s_wcnt[BK_WARPS];
    __shared__ int s_woff[BK_WARPS];

    int qt   = blockIdx.x;
    int tid  = threadIdx.x;
    int warp = tid >> 5;
    int lane = tid & 31;
    int wbase = warp * (BK_PER_LANE * 32);   // 256 batches per warp

    int vals[BK_PER_LANE];
    #pragma unroll
    for (int k = 0; k < BK_PER_LANE; k++)
        vals[k] = __ldg(qus_type + wbase + k * 32 + lane);

    unsigned masks[BK_PER_LANE];
    int cnt = 0;
    #pragma unroll
    for (int k = 0; k < BK_PER_LANE; k++) {
        masks[k] = __ballot_sync(0xFFFFFFFFu, vals[k] == qt);
        cnt += __popc(masks[k]);
    }
    if (lane == 0) s_wcnt[warp] = cnt;
    __syncthreads();

    if (tid == 0) {
        int run = 0;
        #pragma unroll
        for (int w = 0; w < BK_WARPS; w++) { s_woff[w] = run; run += s_wcnt[w]; }
        g_cnt[qt] = run;
    }
    __syncthreads();

    int pos = s_woff[warp];
    int* seg = g_list + qt * BATCH;
    unsigned lt = (1u << lane) - 1u;
    #pragma unroll
    for (int k = 0; k < BK_PER_LANE; k++) {
        if (vals[k] == qt)
            seg[pos + __popc(masks[k] & lt)] = wbase + k * 32 + lane;
        pos += __popc(masks[k]);
    }
}

// ---------------------------------------------------------------------------
// Kernel 2 (PDL secondary): one CTA per (qt, pair) plane.
//   Phase A: 8-way register-blocked float4 streaming copy (64KB in flight
//            per CTA round; halves load->store turnarounds vs 4-way).
//   Phase B: scatter precompacted entries after griddepcontrol.wait.
// ---------------------------------------------------------------------------
__global__ __launch_bounds__(NTHREADS, 4) void fused_plane_kernel(
        const float* __restrict__ src,
        float*       __restrict__ dst,
        const int*   __restrict__ obj_label,
        const float* __restrict__ attention) {
    int plane = blockIdx.x;                 // 0 .. 5849
    int qt = plane / PAIR;
    int p  = plane - qt * PAIR;             // pair index 0..89
    size_t base = (size_t)plane * PLANE;

    const float* s = src + base;
    float*       d = dst + base;
    int tid = threadIdx.x;

    // --- Phase A: copy ---
    int head = (int)((4 - (base & 3)) & 3);         // scalars to reach 16B align
    if (tid < head) __stcs(d + tid, __ldcs(s + tid));

    int nvec = (PLANE - head) >> 2;                 // float4 body count (~5700)
    const float4* s4 = (const float4*)(s + head);
    float4*       d4 = (float4*)(d + head);

    // 8 independent loads in flight, then 8 stores.
    for (int i0 = tid; i0 < nvec; i0 += 8 * NTHREADS) {
        float4 r[8];
        bool v[8];
        #pragma unroll
        for (int k = 0; k < 8; k++) {
            int idx = i0 + k * NTHREADS;
            v[k] = idx < nvec;
            if (v[k]) r[k] = __ldcs(s4 + idx);
        }
        #pragma unroll
        for (int k = 0; k < 8; k++) {
            int idx = i0 + k * NTHREADS;
            if (v[k]) __stcs(d4 + idx, r[k]);
        }
    }

    int tail_start = head + (nvec << 2);
    int ntail = PLANE - tail_start;                 // 0..3 scalars
    if (tid < ntail) __stcs(d + tail_start + tid, __ldcs(s + tail_start + tid));

    // Bucket results visible (bucket kernel finished long ago under the copy)
    asm volatile("griddepcontrol.wait;" ::: "memory");

    __syncthreads();   // plane fully written before this CTA's atomics

    // --- Phase B: scatter the precompacted entries for this qt ---
    int i  = p / (BOX - 1);
    int jj = p - i * (BOX - 1);
    int j  = jj + (jj >= i);

    int n = g_cnt[qt];
    const int* seg = g_list + qt * BATCH;
    for (int u = tid; u < n; u += NTHREADS) {
        int b   = __ldg(seg + u);
        int ol1 = __ldg(obj_label + b * BOX + j);
        int ol2 = __ldg(obj_label + b * BOX + i);
        float a = __ldg(attention + b * BOX + i) * __ldg(attention + b * BOX + j);
        atomicAdd(d + ol1 * NUM_OT + ol2, a);
    }
}

extern "C" void kernel_launch(void* const* d_in, const int* in_sizes, int n_in,
                              void* d_out, int out_size) {
    const int*   obj_label    = (const int*)d_in[0];
    const int*   qus_type     = (const int*)d_in[1];
    const float* attention    = (const float*)d_in[2];
    const float* score_matrix = (const float*)d_in[3];
    float*       out          = (float*)d_out;

    bucket_kernel<<<NUM_QT, BK_THREADS>>>(qus_type);

    cudaLaunchConfig_t cfg = {};
    cfg.gridDim  = dim3(NPLANES);
    cfg.blockDim = dim3(NTHREADS);
    cfg.dynamicSmemBytes = 0;
    cfg.stream = 0;
    cudaLaunchAttribute attr[1];
    attr[0].id = cudaLaunchAttributeProgrammaticStreamSerialization;
    attr[0].val.programmaticStreamSerializationAllowed = 1;
    cfg.attrs = attr;
    cfg.numAttrs = 1;
    cudaLaunchKernelEx(&cfg, fused_plane_kernel,
                       score_matrix, out, obj_label, attention);
}

// round 17
// speedup vs baseline: 2.1816x; 2.1816x over previous
#include <cuda_runtime.h>
#include <cuda_bf16.h>
#include <cstddef>

// Problem constants (from reference)
#define BATCH   8192
#define BOX     10
#define PAIR    90                    // BOX*(BOX-1)
#define NUM_QT  65
#define NUM_OT  151
#define PLANE   (NUM_OT * NUM_OT)     // 22801 floats per (qt,pair) plane
#define NPLANES (NUM_QT * PAIR)       // 5850
#define NTHREADS 512
#define BK_THREADS 1024
#define BK_WARPS   (BK_THREADS / 32)      // 32
#define BK_PER_LANE (BATCH / BK_THREADS)  // 8 values per lane

// Scratch: per-qt compacted batch lists (disjoint segments, no prefix needed)
__device__ int g_list[NUM_QT * BATCH];   // 2 MB
__device__ int g_cnt[NUM_QT];

// ---------------------------------------------------------------------------
// Kernel 1 (PDL primary): per-qt compaction, latency-batched (one memory
// round trip). Fires launch_dependents at entry so kernel 2 overlaps.
// ---------------------------------------------------------------------------
__global__ __launch_bounds__(BK_THREADS) void bucket_kernel(
        const int* __restrict__ qus_type) {
    asm volatile("griddepcontrol.launch_dependents;");

    __shared__ int s_wcnt[BK_WARPS];
    __shared__ int s_woff[BK_WARPS];

    int qt   = blockIdx.x;
    int tid  = threadIdx.x;
    int warp = tid >> 5;
    int lane = tid & 31;
    int wbase = warp * (BK_PER_LANE * 32);   // 256 batches per warp

    int vals[BK_PER_LANE];
    #pragma unroll
    for (int k = 0; k < BK_PER_LANE; k++)
        vals[k] = __ldg(qus_type + wbase + k * 32 + lane);

    unsigned masks[BK_PER_LANE];
    int cnt = 0;
    #pragma unroll
    for (int k = 0; k < BK_PER_LANE; k++) {
        masks[k] = __ballot_sync(0xFFFFFFFFu, vals[k] == qt);
        cnt += __popc(masks[k]);
    }
    if (lane == 0) s_wcnt[warp] = cnt;
    __syncthreads();

    if (tid == 0) {
        int run = 0;
        #pragma unroll
        for (int w = 0; w < BK_WARPS; w++) { s_woff[w] = run; run += s_wcnt[w]; }
        g_cnt[qt] = run;
    }
    __syncthreads();

    int pos = s_woff[warp];
    int* seg = g_list + qt * BATCH;
    unsigned lt = (1u << lane) - 1u;
    #pragma unroll
    for (int k = 0; k < BK_PER_LANE; k++) {
        if (vals[k] == qt)
            seg[pos + __popc(masks[k] & lt)] = wbase + k * 32 + lane;
        pos += __popc(masks[k]);
    }
}

// ---------------------------------------------------------------------------
// Kernel 2 (PDL secondary): one CTA per (qt, pair) plane.
//   Phase A: 8-way register-blocked float4 streaming copy. NO min-blocks
//            clause -> regs float to ~48, the 8 float4s stay in registers
//            (round 15's spill disaster came from the 32-reg cap).
//   Phase B: scatter precompacted entries after griddepcontrol.wait.
// ---------------------------------------------------------------------------
__global__ __launch_bounds__(NTHREADS) void fused_plane_kernel(
        const float* __restrict__ src,
        float*       __restrict__ dst,
        const int*   __restrict__ obj_label,
        const float* __restrict__ attention) {
    int plane = blockIdx.x;                 // 0 .. 5849
    int qt = plane / PAIR;
    int p  = plane - qt * PAIR;             // pair index 0..89
    size_t base = (size_t)plane * PLANE;

    const float* s = src + base;
    float*       d = dst + base;
    int tid = threadIdx.x;

    // --- Phase A: copy ---
    int head = (int)((4 - (base & 3)) & 3);         // scalars to reach 16B align
    if (tid < head) __stcs(d + tid, __ldcs(s + tid));

    int nvec = (PLANE - head) >> 2;                 // float4 body count (~5700)
    const float4* s4 = (const float4*)(s + head);
    float4*       d4 = (float4*)(d + head);

    int i0 = tid;
    // Full 8-way rounds: unguarded, 8 loads in flight then 8 stores.
    for (; i0 + 7 * NTHREADS < nvec; i0 += 8 * NTHREADS) {
        float4 r0 = __ldcs(s4 + i0);
        float4 r1 = __ldcs(s4 + i0 + 1 * NTHREADS);
        float4 r2 = __ldcs(s4 + i0 + 2 * NTHREADS);
        float4 r3 = __ldcs(s4 + i0 + 3 * NTHREADS);
        float4 r4 = __ldcs(s4 + i0 + 4 * NTHREADS);
        float4 r5 = __ldcs(s4 + i0 + 5 * NTHREADS);
        float4 r6 = __ldcs(s4 + i0 + 6 * NTHREADS);
        float4 r7 = __ldcs(s4 + i0 + 7 * NTHREADS);
        __stcs(d4 + i0,                r0);
        __stcs(d4 + i0 + 1 * NTHREADS, r1);
        __stcs(d4 + i0 + 2 * NTHREADS, r2);
        __stcs(d4 + i0 + 3 * NTHREADS, r3);
        __stcs(d4 + i0 + 4 * NTHREADS, r4);
        __stcs(d4 + i0 + 5 * NTHREADS, r5);
        __stcs(d4 + i0 + 6 * NTHREADS, r6);
        __stcs(d4 + i0 + 7 * NTHREADS, r7);
    }
    // Guarded 4-way remainder (proven pattern)
    for (; i0 < nvec; i0 += 4 * NTHREADS) {
        int i1 = i0 + NTHREADS;
        int i2 = i0 + 2 * NTHREADS;
        int i3 = i0 + 3 * NTHREADS;
        float4 r0, r1, r2, r3;
        bool v1 = i1 < nvec, v2 = i2 < nvec, v3 = i3 < nvec;
        r0 = __ldcs(s4 + i0);
        if (v1) r1 = __ldcs(s4 + i1);
        if (v2) r2 = __ldcs(s4 + i2);
        if (v3) r3 = __ldcs(s4 + i3);
        __stcs(d4 + i0, r0);
        if (v1) __stcs(d4 + i1, r1);
        if (v2) __stcs(d4 + i2, r2);
        if (v3) __stcs(d4 + i3, r3);
    }

    int tail_start = head + (nvec << 2);
    int ntail = PLANE - tail_start;                 // 0..3 scalars
    if (tid < ntail) __stcs(d + tail_start + tid, __ldcs(s + tail_start + tid));

    // Bucket results visible (bucket kernel finished long ago under the copy)
    asm volatile("griddepcontrol.wait;" ::: "memory");

    __syncthreads();   // plane fully written before this CTA's atomics

    // --- Phase B: scatter the precompacted entries for this qt ---
    int i  = p / (BOX - 1);
    int jj = p - i * (BOX - 1);
    int j  = jj + (jj >= i);

    int n = g_cnt[qt];
    const int* seg = g_list + qt * BATCH;
    for (int u = tid; u < n; u += NTHREADS) {
        int b   = __ldg(seg + u);
        int ol1 = __ldg(obj_label + b * BOX + j);
        int ol2 = __ldg(obj_label + b * BOX + i);
        float a = __ldg(attention + b * BOX + i) * __ldg(attention + b * BOX + j);
        atomicAdd(d + ol1 * NUM_OT + ol2, a);
    }
}

extern "C" void kernel_launch(void* const* d_in, const int* in_sizes, int n_in,
                              void* d_out, int out_size) {
    const int*   obj_label    = (const int*)d_in[0];
    const int*   qus_type     = (const int*)d_in[1];
    const float* attention    = (const float*)d_in[2];
    const float* score_matrix = (const float*)d_in[3];
    float*       out          = (float*)d_out;

    bucket_kernel<<<NUM_QT, BK_THREADS>>>(qus_type);

    cudaLaunchConfig_t cfg = {};
    cfg.gridDim  = dim3(NPLANES);
    cfg.blockDim = dim3(NTHREADS);
    cfg.dynamicSmemBytes = 0;
    cfg.stream = 0;
    cudaLaunchAttribute attr[1];
    attr[0].id = cudaLaunchAttributeProgrammaticStreamSerialization;
    attr[0].val.programmaticStreamSerializationAllowed = 1;
    cfg.attrs = attr;
    cfg.numAttrs = 1;
    cudaLaunchKernelEx(&cfg, fused_plane_kernel,
                       score_matrix, out, obj_label, attention);
}